// round 6
// baseline (speedup 1.0000x reference)
#include <cuda_runtime.h>
#include <math.h>
#include <stddef.h>

// Problem constants
#define BB 2
#define SS 2048
#define DM 1024
#define NH 16
#define DK 64
#define BHX (BB * NH)   // 32

// ---------------------------------------------------------------------------
// Scratch (device globals; no allocation allowed)
// ---------------------------------------------------------------------------
__device__ float g_Q [(size_t)BB * SS * DM];   // projected Q  [B*S, 1024]
__device__ float g_Kp[(size_t)BB * SS * DK];   // projected K  [B*S, 64]
__device__ float g_Vp[(size_t)BB * SS * DK];   // projected V  [B*S, 64]
__device__ float g_AO[(size_t)BB * SS * DM];   // attn output in reference reshape layout
// Fallback scratch for attn if it's not part of d_out (536 MB, bss/zero-init)
__device__ float g_attn_scratch[(size_t)BB * NH * SS * SS];

// ---------------------------------------------------------------------------
// Generic tiled GEMM with bias: C[M,N] = A[M,K] @ W[K,N] + bias[N]
// 64x64 tile, 256 threads, 4x4 per thread, BK=16.
// ---------------------------------------------------------------------------
__global__ void gemm_bias_kernel(const float* __restrict__ A,
                                 const float* __restrict__ W,
                                 const float* __restrict__ bias,
                                 float* __restrict__ C,
                                 int M, int K, int N) {
    __shared__ float As[16][65];   // [k][m], padded
    __shared__ float Ws[16][64];   // [k][n]

    const int tid = threadIdx.x;
    const int tx = tid & 15;
    const int ty = tid >> 4;
    const int bm = blockIdx.x * 64;
    const int bn = blockIdx.y * 64;

    float acc[4][4] = {};

    for (int k0 = 0; k0 < K; k0 += 16) {
        // A tile 64x16 -> As[k][m]
        #pragma unroll
        for (int i = tid; i < 64 * 16; i += 256) {
            int m = i >> 4, k = i & 15;
            As[k][m] = A[(size_t)(bm + m) * K + k0 + k];
        }
        // W tile 16x64 -> Ws[k][n]; fully coalesced
        #pragma unroll
        for (int i = tid; i < 16 * 64; i += 256) {
            int k = i >> 6, n = i & 63;
            Ws[k][n] = W[(size_t)(k0 + k) * N + bn + n];
        }
        __syncthreads();

        #pragma unroll
        for (int k = 0; k < 16; k++) {
            float a[4];
            #pragma unroll
            for (int i = 0; i < 4; i++) a[i] = As[k][ty * 4 + i];
            float4 bv = *reinterpret_cast<const float4*>(&Ws[k][tx * 4]);
            float b[4] = {bv.x, bv.y, bv.z, bv.w};
            #pragma unroll
            for (int i = 0; i < 4; i++)
                #pragma unroll
                for (int j = 0; j < 4; j++)
                    acc[i][j] = fmaf(a[i], b[j], acc[i][j]);
        }
        __syncthreads();
    }

    #pragma unroll
    for (int i = 0; i < 4; i++) {
        int m = bm + ty * 4 + i;
        #pragma unroll
        for (int j = 0; j < 4; j++) {
            int n = bn + tx * 4 + j;
            C[(size_t)m * N + n] = acc[i][j] + bias[n];
        }
    }
}

// ---------------------------------------------------------------------------
// Scores: attn_pre[bh, i, j] = (Q[b,i,h,:] . K[b,j,:]) / sqrt(64)
// grid: (S/64, S/64, B*H)
// ---------------------------------------------------------------------------
__global__ void scores_kernel(float* __restrict__ attn) {
    const int bh = blockIdx.z;
    const int b = bh >> 4;
    const int h = bh & 15;
    const int bm = blockIdx.x * 64;
    const int bn = blockIdx.y * 64;

    __shared__ float Qs[64][DK + 1];   // [m][d]
    __shared__ float Ks[64][DK + 1];   // [n][d]

    const int tid = threadIdx.x;

    #pragma unroll
    for (int i = tid; i < 64 * DK; i += 256) {
        int r = i >> 6, d = i & 63;
        Qs[r][d] = g_Q [(size_t)(b * SS + bm + r) * DM + h * DK + d];
        Ks[r][d] = g_Kp[(size_t)(b * SS + bn + r) * DK + d];
    }
    __syncthreads();

    const int tx = tid & 15;
    const int ty = tid >> 4;
    float acc[4][4] = {};

    #pragma unroll 8
    for (int d = 0; d < DK; d++) {
        float a[4], bb[4];
        #pragma unroll
        for (int i = 0; i < 4; i++) a[i]  = Qs[ty * 4 + i][d];
        #pragma unroll
        for (int j = 0; j < 4; j++) bb[j] = Ks[tx * 4 + j][d];
        #pragma unroll
        for (int i = 0; i < 4; i++)
            #pragma unroll
            for (int j = 0; j < 4; j++)
                acc[i][j] = fmaf(a[i], bb[j], acc[i][j]);
    }

    const float scale = 0.125f;   // 1/sqrt(64)
    #pragma unroll
    for (int i = 0; i < 4; i++) {
        size_t row = (size_t)bh * SS + bm + ty * 4 + i;
        #pragma unroll
        for (int j = 0; j < 4; j++)
            attn[row * SS + bn + tx * 4 + j] = acc[i][j] * scale;
    }
}

// ---------------------------------------------------------------------------
// Row softmax over the last dim (S=2048). One block per row. In-place.
// ---------------------------------------------------------------------------
__global__ void softmax_kernel(float* __restrict__ attn) {
    const size_t row = blockIdx.x;
    float* p = attn + row * SS;
    const int tid = threadIdx.x;   // 256 threads, 8 elems each

    __shared__ float red[256];

    float v[8];
    float m = -INFINITY;
    #pragma unroll
    for (int i = 0; i < 8; i++) {
        v[i] = p[tid + i * 256];
        m = fmaxf(m, v[i]);
    }
    red[tid] = m;
    __syncthreads();
    #pragma unroll
    for (int s = 128; s > 0; s >>= 1) {
        if (tid < s) red[tid] = fmaxf(red[tid], red[tid + s]);
        __syncthreads();
    }
    m = red[0];
    __syncthreads();

    float sum = 0.f;
    #pragma unroll
    for (int i = 0; i < 8; i++) {
        v[i] = __expf(v[i] - m);
        sum += v[i];
    }
    red[tid] = sum;
    __syncthreads();
    #pragma unroll
    for (int s = 128; s > 0; s >>= 1) {
        if (tid < s) red[tid] += red[tid + s];
        __syncthreads();
    }
    const float inv = 1.f / red[0];

    #pragma unroll
    for (int i = 0; i < 8; i++)
        p[tid + i * 256] = v[i] * inv;
}

// ---------------------------------------------------------------------------
// heads = attn @ V, written in the REFERENCE layout:
//   heads[b][h][s_q][d]  (flat offset h*S*DK + s_q*DK + d per batch)
//   reinterpreted row-major as [S, D_MODEL]:
//     row  = h*128 + (s_q >> 4)
//     col  = (s_q & 15)*64 + d
// grid: (S/64, B*H); 64 q-rows x 64 d-cols per block.
// ---------------------------------------------------------------------------
__global__ void av_kernel(const float* __restrict__ attn) {
    const int bh = blockIdx.y;
    const int b = bh >> 4;
    const int h = bh & 15;
    const int bm = blockIdx.x * 64;

    const float* A = attn + (size_t)bh * SS * SS;

    __shared__ float As[16][65];   // [k][m]
    __shared__ float Vs[16][64];   // [k][d]

    const int tid = threadIdx.x;
    const int tx = tid & 15;
    const int ty = tid >> 4;
    float acc[4][4] = {};

    for (int k0 = 0; k0 < SS; k0 += 16) {
        #pragma unroll
        for (int i = tid; i < 64 * 16; i += 256) {
            int m = i >> 4, k = i & 15;
            As[k][m] = A[(size_t)(bm + m) * SS + k0 + k];
        }
        #pragma unroll
        for (int i = tid; i < 16 * 64; i += 256) {
            int k = i >> 6, d = i & 63;
            Vs[k][d] = g_Vp[(size_t)(b * SS + k0 + k) * DK + d];
        }
        __syncthreads();

        #pragma unroll
        for (int k = 0; k < 16; k++) {
            float a[4];
            #pragma unroll
            for (int i = 0; i < 4; i++) a[i] = As[k][ty * 4 + i];
            float4 bv = *reinterpret_cast<const float4*>(&Vs[k][tx * 4]);
            float bb[4] = {bv.x, bv.y, bv.z, bv.w};
            #pragma unroll
            for (int i = 0; i < 4; i++)
                #pragma unroll
                for (int j = 0; j < 4; j++)
                    acc[i][j] = fmaf(a[i], bb[j], acc[i][j]);
        }
        __syncthreads();
    }

    // Scrambled-reshape store (matches reference heads.reshape(B,S,D_MODEL)).
    #pragma unroll
    for (int i = 0; i < 4; i++) {
        int sq = bm + ty * 4 + i;                          // query index
        size_t row = (size_t)b * SS + h * 128 + (sq >> 4); // output row in [B*S)
        int cbase = (sq & 15) * 64 + tx * 4;               // output col base
        #pragma unroll
        for (int j = 0; j < 4; j++)
            g_AO[row * DM + cbase + j] = acc[i][j];
    }
}

// ---------------------------------------------------------------------------
// Launch
// ---------------------------------------------------------------------------
extern "C" void kernel_launch(void* const* d_in, const int* in_sizes, int n_in,
                              void* d_out, int out_size) {
    const float* query = (const float*)d_in[0];
    const float* key_  = (const float*)d_in[1];
    const float* value = (const float*)d_in[2];
    const float* w_q   = (const float*)d_in[3];
    const float* b_q   = (const float*)d_in[4];
    const float* w_k   = (const float*)d_in[5];
    const float* b_k   = (const float*)d_in[6];
    const float* w_v   = (const float*)d_in[7];
    const float* b_v   = (const float*)d_in[8];
    const float* w_o   = (const float*)d_in[9];
    const float* b_o   = (const float*)d_in[10];

    float *Qp, *Kp, *Vp, *AO, *attn_scr;
    cudaGetSymbolAddress((void**)&Qp, g_Q);
    cudaGetSymbolAddress((void**)&Kp, g_Kp);
    cudaGetSymbolAddress((void**)&Vp, g_Vp);
    cudaGetSymbolAddress((void**)&AO, g_AO);
    cudaGetSymbolAddress((void**)&attn_scr, g_attn_scratch);

    float* out = (float*)d_out;
    const size_t OUT_ELEMS  = (size_t)BB * SS * DM;                 // 4,194,304
    const size_t ATTN_ELEMS = (size_t)BB * NH * SS * SS;            // 134,217,728

    // If the harness output holds the (out, attn) tuple, write attn in-place.
    float* attn = ((size_t)out_size >= OUT_ELEMS + ATTN_ELEMS)
                      ? (out + OUT_ELEMS)
                      : attn_scr;

    const int M = BB * SS;   // 4096
    dim3 thr(256);

    // Projections
    gemm_bias_kernel<<<dim3(M / 64, DM / 64), thr>>>(query, w_q, b_q, Qp, M, DM, DM);
    gemm_bias_kernel<<<dim3(M / 64, 1),       thr>>>(key_,  w_k, b_k, Kp, M, DM, DK);
    gemm_bias_kernel<<<dim3(M / 64, 1),       thr>>>(value, w_v, b_v, Vp, M, DM, DK);

    // Scores + softmax
    scores_kernel<<<dim3(SS / 64, SS / 64, BHX), thr>>>(attn);
    softmax_kernel<<<dim3((unsigned)((size_t)BHX * SS)), thr>>>(attn);

    // attn @ V (reference reshape layout)
    av_kernel<<<dim3(SS / 64, BHX), thr>>>(attn);

    // Output projection
    gemm_bias_kernel<<<dim3(M / 64, DM / 64), thr>>>(AO, w_o, b_o, out, M, DM, DM);
}

// round 7
// speedup vs baseline: 2.1960x; 2.1960x over previous
#include <cuda_runtime.h>
#include <math.h>
#include <stddef.h>

// Problem constants
#define BB 2
#define SS 2048
#define DM 1024
#define NH 16
#define DK 64
#define BHX (BB * NH)   // 32

// ---------------------------------------------------------------------------
// Scratch (device globals; no allocation allowed)
// ---------------------------------------------------------------------------
__device__ float g_Q [(size_t)BB * SS * DM];   // projected Q  [B*S, 1024]
__device__ float g_Kp[(size_t)BB * SS * DK];   // projected K  [B*S, 64]
__device__ float g_Vp[(size_t)BB * SS * DK];   // projected V  [B*S, 64]
__device__ float g_AO[(size_t)BB * SS * DM];   // attn output in reference reshape layout
__device__ float g_attn_scratch[(size_t)BB * NH * SS * SS];  // fallback attn

// ---------------------------------------------------------------------------
// TF32 helpers (legacy mma.sync path; fragments are standard Ampere+ layouts)
// ---------------------------------------------------------------------------
__device__ __forceinline__ unsigned f2tf(float x) {
    unsigned r;
    asm("cvt.rna.tf32.f32 %0, %1;" : "=r"(r) : "f"(x));
    return r;
}

__device__ __forceinline__ void mma_tf32(float c[4], const unsigned a[4], const unsigned b[2]) {
    asm volatile(
        "mma.sync.aligned.m16n8k8.row.col.f32.tf32.tf32.f32 "
        "{%0,%1,%2,%3}, {%4,%5,%6,%7}, {%8,%9}, {%0,%1,%2,%3};"
        : "+f"(c[0]), "+f"(c[1]), "+f"(c[2]), "+f"(c[3])
        : "r"(a[0]), "r"(a[1]), "r"(a[2]), "r"(a[3]), "r"(b[0]), "r"(b[1]));
}

// ---------------------------------------------------------------------------
// Generic tiled GEMM with bias: C[M,N] = A[M,K] @ W[K,N] + bias[N]
// 64x64 tile, 256 threads, 4x4 per thread, BK=16.  (fp32 SIMT; used for the
// exactness-critical projections.)  As padded to 68 so a-reads are LDS.128.
// ---------------------------------------------------------------------------
__global__ void gemm_bias_kernel(const float* __restrict__ A,
                                 const float* __restrict__ W,
                                 const float* __restrict__ bias,
                                 float* __restrict__ C,
                                 int M, int K, int N) {
    __shared__ float As[16][68];   // [k][m], padded so rows are 16B-aligned
    __shared__ float Ws[16][64];   // [k][n]

    const int tid = threadIdx.x;
    const int tx = tid & 15;
    const int ty = tid >> 4;
    const int bm = blockIdx.x * 64;
    const int bn = blockIdx.y * 64;

    float acc[4][4] = {};

    for (int k0 = 0; k0 < K; k0 += 16) {
        #pragma unroll
        for (int i = tid; i < 64 * 16; i += 256) {
            int m = i >> 4, k = i & 15;
            As[k][m] = A[(size_t)(bm + m) * K + k0 + k];
        }
        #pragma unroll
        for (int i = tid; i < 16 * 64; i += 256) {
            int k = i >> 6, n = i & 63;
            Ws[k][n] = W[(size_t)(k0 + k) * N + bn + n];
        }
        __syncthreads();

        #pragma unroll
        for (int k = 0; k < 16; k++) {
            float4 avv = *reinterpret_cast<const float4*>(&As[k][ty * 4]);
            float a[4] = {avv.x, avv.y, avv.z, avv.w};
            float4 bv = *reinterpret_cast<const float4*>(&Ws[k][tx * 4]);
            float b[4] = {bv.x, bv.y, bv.z, bv.w};
            #pragma unroll
            for (int i = 0; i < 4; i++)
                #pragma unroll
                for (int j = 0; j < 4; j++)
                    acc[i][j] = fmaf(a[i], b[j], acc[i][j]);
        }
        __syncthreads();
    }

    #pragma unroll
    for (int i = 0; i < 4; i++) {
        int m = bm + ty * 4 + i;
        #pragma unroll
        for (int j = 0; j < 4; j++) {
            int n = bn + tx * 4 + j;
            C[(size_t)m * N + n] = acc[i][j] + bias[n];
        }
    }
}

// ---------------------------------------------------------------------------
// Scores via TF32 tensor MMA:
//   attn_pre[bh, i, j] = (Q[b,i,h,:] . K[b,j,:]) * 0.125
// Block: 128(m) x 128(n); 8 warps as 2(m) x 4(n); warp = 64x32
//   -> 4 m-tiles(16) x 4 n-tiles(8), K=64 in two 32-chunks, k-steps of 8.
// grid: (S/128, S/128, B*H)
// ---------------------------------------------------------------------------
__global__ void scores_tc_kernel(float* __restrict__ attn) {
    const int bh = blockIdx.z;
    const int b = bh >> 4;
    const int h = bh & 15;
    const int bm = blockIdx.x * 128;
    const int bn = blockIdx.y * 128;

    __shared__ unsigned Qs[128][36];   // [m][k-chunk], pad->conflict-free frags
    __shared__ unsigned Ks[128][36];   // [n][k-chunk]

    const int tid = threadIdx.x;
    const int warp = tid >> 5;
    const int lane = tid & 31;
    const int wm = (warp >> 2) * 64;   // 0 or 64
    const int wn = (warp & 3) * 32;    // 0,32,64,96
    const int lr = lane >> 2;          // 0..7
    const int lc = lane & 3;           // 0..3

    float c[4][4][4] = {};             // [mtile][ntile][frag]

    for (int k0 = 0; k0 < DK; k0 += 32) {
        // Load Q tile 128x32 (convert to tf32)
        {
            const int r = tid >> 1;
            const int cb = (tid & 1) * 16;
            const float* src = &g_Q[(size_t)(b * SS + bm + r) * DM + h * DK + k0 + cb];
            #pragma unroll
            for (int i = 0; i < 4; i++) {
                float4 v = *reinterpret_cast<const float4*>(src + i * 4);
                Qs[r][cb + i * 4 + 0] = f2tf(v.x);
                Qs[r][cb + i * 4 + 1] = f2tf(v.y);
                Qs[r][cb + i * 4 + 2] = f2tf(v.z);
                Qs[r][cb + i * 4 + 3] = f2tf(v.w);
            }
            const float* ksrc = &g_Kp[(size_t)(b * SS + bn + r) * DK + k0 + cb];
            #pragma unroll
            for (int i = 0; i < 4; i++) {
                float4 v = *reinterpret_cast<const float4*>(ksrc + i * 4);
                Ks[r][cb + i * 4 + 0] = f2tf(v.x);
                Ks[r][cb + i * 4 + 1] = f2tf(v.y);
                Ks[r][cb + i * 4 + 2] = f2tf(v.z);
                Ks[r][cb + i * 4 + 3] = f2tf(v.w);
            }
        }
        __syncthreads();

        #pragma unroll
        for (int ks = 0; ks < 4; ks++) {
            const int kb = ks * 8;
            unsigned a[4][4], bf[4][2];
            #pragma unroll
            for (int mt = 0; mt < 4; mt++) {
                int r0 = wm + mt * 16 + lr;
                a[mt][0] = Qs[r0    ][kb + lc];
                a[mt][1] = Qs[r0 + 8][kb + lc];
                a[mt][2] = Qs[r0    ][kb + 4 + lc];
                a[mt][3] = Qs[r0 + 8][kb + 4 + lc];
            }
            #pragma unroll
            for (int nt = 0; nt < 4; nt++) {
                int n0 = wn + nt * 8 + lr;
                bf[nt][0] = Ks[n0][kb + lc];
                bf[nt][1] = Ks[n0][kb + 4 + lc];
            }
            #pragma unroll
            for (int mt = 0; mt < 4; mt++)
                #pragma unroll
                for (int nt = 0; nt < 4; nt++)
                    mma_tf32(c[mt][nt], a[mt], bf[nt]);
        }
        __syncthreads();
    }

    // Epilogue: scale by 1/sqrt(64) and store.
    const float scale = 0.125f;
    #pragma unroll
    for (int mt = 0; mt < 4; mt++) {
        #pragma unroll
        for (int half = 0; half < 2; half++) {
            int m = bm + wm + mt * 16 + lr + half * 8;
            size_t rowbase = ((size_t)bh * SS + m) * SS;
            #pragma unroll
            for (int nt = 0; nt < 4; nt++) {
                int n = bn + wn + nt * 8 + lc * 2;
                float2 v;
                v.x = c[mt][nt][half * 2 + 0] * scale;
                v.y = c[mt][nt][half * 2 + 1] * scale;
                *reinterpret_cast<float2*>(&attn[rowbase + n]) = v;
            }
        }
    }
}

// ---------------------------------------------------------------------------
// Row softmax over the last dim (S=2048). One block per row. In-place.
// ---------------------------------------------------------------------------
__global__ void softmax_kernel(float* __restrict__ attn) {
    const size_t row = blockIdx.x;
    float* p = attn + row * SS;
    const int tid = threadIdx.x;   // 256 threads, 8 elems each

    __shared__ float red[256];

    float v[8];
    float m = -INFINITY;
    #pragma unroll
    for (int i = 0; i < 8; i++) {
        v[i] = p[tid + i * 256];
        m = fmaxf(m, v[i]);
    }
    red[tid] = m;
    __syncthreads();
    #pragma unroll
    for (int s = 128; s > 0; s >>= 1) {
        if (tid < s) red[tid] = fmaxf(red[tid], red[tid + s]);
        __syncthreads();
    }
    m = red[0];
    __syncthreads();

    float sum = 0.f;
    #pragma unroll
    for (int i = 0; i < 8; i++) {
        v[i] = __expf(v[i] - m);
        sum += v[i];
    }
    red[tid] = sum;
    __syncthreads();
    #pragma unroll
    for (int s = 128; s > 0; s >>= 1) {
        if (tid < s) red[tid] += red[tid + s];
        __syncthreads();
    }
    const float inv = 1.f / red[0];

    #pragma unroll
    for (int i = 0; i < 8; i++)
        p[tid + i * 256] = v[i] * inv;
}

// ---------------------------------------------------------------------------
// heads = attn @ V via TF32 tensor MMA, stored in the REFERENCE reshape layout:
//   row = b*S + h*128 + (s_q >> 4),  col = (s_q & 15)*64 + d
// Block: 128(m) x 64(n); 8 warps as 4(m) x 2(n); warp = 32x32
//   -> 2 m-tiles x 4 n-tiles.  K = S = 2048 in 32-chunks.
// grid: (S/128, B*H)
// ---------------------------------------------------------------------------
__global__ void av_tc_kernel(const float* __restrict__ attn) {
    const int bh = blockIdx.y;
    const int b = bh >> 4;
    const int h = bh & 15;
    const int bm = blockIdx.x * 128;

    const float* A = attn + (size_t)bh * SS * SS;

    __shared__ unsigned As_[128][36];  // attn tile [m][k-chunk]
    __shared__ unsigned Vs[32][68];    // V tile [k][n], pad->conflict-free

    const int tid = threadIdx.x;
    const int warp = tid >> 5;
    const int lane = tid & 31;
    const int wm = (warp >> 1) * 32;   // 0,32,64,96
    const int wn = (warp & 1) * 32;    // 0,32
    const int lr = lane >> 2;
    const int lc = lane & 3;

    float c[2][4][4] = {};

    for (int k0 = 0; k0 < SS; k0 += 32) {
        // attn tile 128x32
        {
            const int r = tid >> 1;
            const int cb = (tid & 1) * 16;
            const float* src = &A[(size_t)(bm + r) * SS + k0 + cb];
            #pragma unroll
            for (int i = 0; i < 4; i++) {
                float4 v = *reinterpret_cast<const float4*>(src + i * 4);
                As_[r][cb + i * 4 + 0] = f2tf(v.x);
                As_[r][cb + i * 4 + 1] = f2tf(v.y);
                As_[r][cb + i * 4 + 2] = f2tf(v.z);
                As_[r][cb + i * 4 + 3] = f2tf(v.w);
            }
        }
        // V tile 32x64
        {
            const int r = tid >> 3;            // 0..31
            const int cb = (tid & 7) * 8;      // 0..56
            const float* src = &g_Vp[(size_t)(b * SS + k0 + r) * DK + cb];
            #pragma unroll
            for (int i = 0; i < 2; i++) {
                float4 v = *reinterpret_cast<const float4*>(src + i * 4);
                Vs[r][cb + i * 4 + 0] = f2tf(v.x);
                Vs[r][cb + i * 4 + 1] = f2tf(v.y);
                Vs[r][cb + i * 4 + 2] = f2tf(v.z);
                Vs[r][cb + i * 4 + 3] = f2tf(v.w);
            }
        }
        __syncthreads();

        #pragma unroll
        for (int ks = 0; ks < 4; ks++) {
            const int kb = ks * 8;
            unsigned a[2][4], bf[4][2];
            #pragma unroll
            for (int mt = 0; mt < 2; mt++) {
                int r0 = wm + mt * 16 + lr;
                a[mt][0] = As_[r0    ][kb + lc];
                a[mt][1] = As_[r0 + 8][kb + lc];
                a[mt][2] = As_[r0    ][kb + 4 + lc];
                a[mt][3] = As_[r0 + 8][kb + 4 + lc];
            }
            #pragma unroll
            for (int nt = 0; nt < 4; nt++) {
                int n0 = wn + nt * 8 + lr;
                bf[nt][0] = Vs[kb + lc    ][n0];
                bf[nt][1] = Vs[kb + 4 + lc][n0];
            }
            #pragma unroll
            for (int mt = 0; mt < 2; mt++)
                #pragma unroll
                for (int nt = 0; nt < 4; nt++)
                    mma_tf32(c[mt][nt], a[mt], bf[nt]);
        }
        __syncthreads();
    }

    // Scrambled-reshape store (matches reference heads.reshape(B,S,D_MODEL)).
    #pragma unroll
    for (int mt = 0; mt < 2; mt++) {
        #pragma unroll
        for (int half = 0; half < 2; half++) {
            int sq = bm + wm + mt * 16 + lr + half * 8;       // query index
            size_t row = (size_t)b * SS + h * 128 + (sq >> 4);
            int cpart = (sq & 15) * 64;
            #pragma unroll
            for (int nt = 0; nt < 4; nt++) {
                int d = wn + nt * 8 + lc * 2;
                float2 v;
                v.x = c[mt][nt][half * 2 + 0];
                v.y = c[mt][nt][half * 2 + 1];
                *reinterpret_cast<float2*>(&g_AO[row * DM + cpart + d]) = v;
            }
        }
    }
}

// ---------------------------------------------------------------------------
// Launch
// ---------------------------------------------------------------------------
extern "C" void kernel_launch(void* const* d_in, const int* in_sizes, int n_in,
                              void* d_out, int out_size) {
    const float* query = (const float*)d_in[0];
    const float* key_  = (const float*)d_in[1];
    const float* value = (const float*)d_in[2];
    const float* w_q   = (const float*)d_in[3];
    const float* b_q   = (const float*)d_in[4];
    const float* w_k   = (const float*)d_in[5];
    const float* b_k   = (const float*)d_in[6];
    const float* w_v   = (const float*)d_in[7];
    const float* b_v   = (const float*)d_in[8];
    const float* w_o   = (const float*)d_in[9];
    const float* b_o   = (const float*)d_in[10];

    float *Qp, *Kp, *Vp, *AO, *attn_scr;
    cudaGetSymbolAddress((void**)&Qp, g_Q);
    cudaGetSymbolAddress((void**)&Kp, g_Kp);
    cudaGetSymbolAddress((void**)&Vp, g_Vp);
    cudaGetSymbolAddress((void**)&AO, g_AO);
    cudaGetSymbolAddress((void**)&attn_scr, g_attn_scratch);

    float* out = (float*)d_out;
    const size_t OUT_ELEMS  = (size_t)BB * SS * DM;
    const size_t ATTN_ELEMS = (size_t)BB * NH * SS * SS;

    float* attn = ((size_t)out_size >= OUT_ELEMS + ATTN_ELEMS)
                      ? (out + OUT_ELEMS)
                      : attn_scr;

    const int M = BB * SS;   // 4096
    dim3 thr(256);

    // Projections (exact fp32)
    gemm_bias_kernel<<<dim3(M / 64, DM / 64), thr>>>(query, w_q, b_q, Qp, M, DM, DM);
    gemm_bias_kernel<<<dim3(M / 64, 1),       thr>>>(key_,  w_k, b_k, Kp, M, DM, DK);
    gemm_bias_kernel<<<dim3(M / 64, 1),       thr>>>(value, w_v, b_v, Vp, M, DM, DK);

    // Scores (tf32 tensor core) + softmax
    scores_tc_kernel<<<dim3(SS / 128, SS / 128, BHX), thr>>>(attn);
    softmax_kernel<<<dim3((unsigned)((size_t)BHX * SS)), thr>>>(attn);

    // attn @ V (tf32 tensor core, reference reshape layout)
    av_tc_kernel<<<dim3(SS / 128, BHX), thr>>>(attn);

    // Output projection (exact fp32)
    gemm_bias_kernel<<<dim3(M / 64, DM / 64), thr>>>(AO, w_o, b_o, out, M, DM, DM);
}

// round 9
// speedup vs baseline: 2.4946x; 1.1360x over previous
#include <cuda_runtime.h>
#include <math.h>
#include <stddef.h>

// Problem constants
#define BB 2
#define SS 2048
#define DM 1024
#define NH 16
#define DK 64
#define BHX (BB * NH)   // 32

// ---------------------------------------------------------------------------
// Scratch (device globals; no allocation allowed)
// ---------------------------------------------------------------------------
__device__ float g_Q [(size_t)BB * SS * DM];   // projected Q  [B*S, 1024]
__device__ float g_Kp[(size_t)BB * SS * DK];   // projected K  [B*S, 64]
__device__ float g_Vp[(size_t)BB * SS * DK];   // projected V  [B*S, 64]
__device__ float g_AO[(size_t)BB * SS * DM];   // attn output in reference reshape layout
__device__ float g_attn_scratch[(size_t)BB * NH * SS * SS];  // fallback attn

// ---------------------------------------------------------------------------
// TF32 helpers (legacy mma.sync path; fragment layouts validated in R7)
// ---------------------------------------------------------------------------
__device__ __forceinline__ unsigned f2tf(float x) {
    unsigned r;
    asm("cvt.rna.tf32.f32 %0, %1;" : "=r"(r) : "f"(x));
    return r;
}

__device__ __forceinline__ void mma_tf32(float c[4], const unsigned a[4], const unsigned b[2]) {
    asm volatile(
        "mma.sync.aligned.m16n8k8.row.col.f32.tf32.tf32.f32 "
        "{%0,%1,%2,%3}, {%4,%5,%6,%7}, {%8,%9}, {%0,%1,%2,%3};"
        : "+f"(c[0]), "+f"(c[1]), "+f"(c[2]), "+f"(c[3])
        : "r"(a[0]), "r"(a[1]), "r"(a[2]), "r"(a[3]), "r"(b[0]), "r"(b[1]));
}

// Split x into tf32 hi + tf32 lo (3xTF32 technique; near-fp32 accuracy).
__device__ __forceinline__ void split_tf32(float x, unsigned& hi, unsigned& lo) {
    hi = f2tf(x);
    lo = f2tf(x - __uint_as_float(hi));
}

// ---------------------------------------------------------------------------
// SIMT fp32 GEMM with bias (kept for the small K/V projections, N=64):
// C[M,N] = A[M,K] @ W[K,N] + bias[N]; 64x64 tile, 256 thr, 4x4/thread, BK=16.
// ---------------------------------------------------------------------------
__global__ void gemm_bias_kernel(const float* __restrict__ A,
                                 const float* __restrict__ W,
                                 const float* __restrict__ bias,
                                 float* __restrict__ C,
                                 int M, int K, int N) {
    __shared__ float As[16][68];
    __shared__ float Ws[16][64];

    const int tid = threadIdx.x;
    const int tx = tid & 15;
    const int ty = tid >> 4;
    const int bm = blockIdx.x * 64;
    const int bn = blockIdx.y * 64;

    float acc[4][4] = {};

    for (int k0 = 0; k0 < K; k0 += 16) {
        #pragma unroll
        for (int i = tid; i < 64 * 16; i += 256) {
            int m = i >> 4, k = i & 15;
            As[k][m] = A[(size_t)(bm + m) * K + k0 + k];
        }
        #pragma unroll
        for (int i = tid; i < 16 * 64; i += 256) {
            int k = i >> 6, n = i & 63;
            Ws[k][n] = W[(size_t)(k0 + k) * N + bn + n];
        }
        __syncthreads();

        #pragma unroll
        for (int k = 0; k < 16; k++) {
            float4 avv = *reinterpret_cast<const float4*>(&As[k][ty * 4]);
            float a[4] = {avv.x, avv.y, avv.z, avv.w};
            float4 bv = *reinterpret_cast<const float4*>(&Ws[k][tx * 4]);
            float b[4] = {bv.x, bv.y, bv.z, bv.w};
            #pragma unroll
            for (int i = 0; i < 4; i++)
                #pragma unroll
                for (int j = 0; j < 4; j++)
                    acc[i][j] = fmaf(a[i], b[j], acc[i][j]);
        }
        __syncthreads();
    }

    #pragma unroll
    for (int i = 0; i < 4; i++) {
        int m = bm + ty * 4 + i;
        #pragma unroll
        for (int j = 0; j < 4; j++) {
            int n = bn + tx * 4 + j;
            C[(size_t)m * N + n] = acc[i][j] + bias[n];
        }
    }
}

// ---------------------------------------------------------------------------
// 3xTF32 tensor-core GEMM with bias (near-fp32 accuracy):
//   C[M,N] = A[M,K] @ W[K,N] + bias[N]
// Block 128m x 128n; 8 warps as 2(m) x 4(n); warp = 64x32; BK=16.
// W transposed to [n][k] in smem on load.  Requires M%128==0, N%128==0, K%16==0.
// ---------------------------------------------------------------------------
__global__ void gemm_bias_tf32x3_kernel(const float* __restrict__ A,
                                        const float* __restrict__ W,
                                        const float* __restrict__ bias,
                                        float* __restrict__ C,
                                        int M, int K, int N) {
    __shared__ unsigned Ah[128][20];   // [m][k], padded
    __shared__ unsigned Al[128][20];
    __shared__ unsigned Wh[128][20];   // [n][k], padded
    __shared__ unsigned Wl[128][20];

    const int tid = threadIdx.x;
    const int warp = tid >> 5;
    const int lane = tid & 31;
    const int wm = (warp >> 2) * 64;   // 0 or 64
    const int wn = (warp & 3) * 32;    // 0,32,64,96
    const int lr = lane >> 2;          // 0..7
    const int lc = lane & 3;           // 0..3
    const int bm = blockIdx.x * 128;
    const int bn = blockIdx.y * 128;

    float c[4][4][4] = {};             // [mtile][ntile][frag]

    for (int k0 = 0; k0 < K; k0 += 16) {
        // A tile 128x16 -> hi/lo
        {
            const int r = tid >> 1;            // 0..127
            const int cb = (tid & 1) * 8;      // 0 or 8
            const float* src = &A[(size_t)(bm + r) * K + k0 + cb];
            #pragma unroll
            for (int i = 0; i < 2; i++) {
                float4 v = *reinterpret_cast<const float4*>(src + i * 4);
                unsigned hi, lo;
                split_tf32(v.x, hi, lo); Ah[r][cb + i*4 + 0] = hi; Al[r][cb + i*4 + 0] = lo;
                split_tf32(v.y, hi, lo); Ah[r][cb + i*4 + 1] = hi; Al[r][cb + i*4 + 1] = lo;
                split_tf32(v.z, hi, lo); Ah[r][cb + i*4 + 2] = hi; Al[r][cb + i*4 + 2] = lo;
                split_tf32(v.w, hi, lo); Ah[r][cb + i*4 + 3] = hi; Al[r][cb + i*4 + 3] = lo;
            }
        }
        // W tile 16x128 -> transpose to [n][k], hi/lo
        {
            const int kk = tid >> 4;           // 0..15
            const int nb = (tid & 15) * 8;     // 0..120
            const float* src = &W[(size_t)(k0 + kk) * N + bn + nb];
            #pragma unroll
            for (int i = 0; i < 2; i++) {
                float4 v = *reinterpret_cast<const float4*>(src + i * 4);
                unsigned hi, lo;
                split_tf32(v.x, hi, lo); Wh[nb + i*4 + 0][kk] = hi; Wl[nb + i*4 + 0][kk] = lo;
                split_tf32(v.y, hi, lo); Wh[nb + i*4 + 1][kk] = hi; Wl[nb + i*4 + 1][kk] = lo;
                split_tf32(v.z, hi, lo); Wh[nb + i*4 + 2][kk] = hi; Wl[nb + i*4 + 2][kk] = lo;
                split_tf32(v.w, hi, lo); Wh[nb + i*4 + 3][kk] = hi; Wl[nb + i*4 + 3][kk] = lo;
            }
        }
        __syncthreads();

        #pragma unroll
        for (int ks = 0; ks < 2; ks++) {
            const int kb = ks * 8;
            unsigned ah[4][4], al[4][4], bh[4][2], bl[4][2];
            #pragma unroll
            for (int mt = 0; mt < 4; mt++) {
                int r0 = wm + mt * 16 + lr;
                ah[mt][0] = Ah[r0    ][kb + lc];
                ah[mt][1] = Ah[r0 + 8][kb + lc];
                ah[mt][2] = Ah[r0    ][kb + 4 + lc];
                ah[mt][3] = Ah[r0 + 8][kb + 4 + lc];
                al[mt][0] = Al[r0    ][kb + lc];
                al[mt][1] = Al[r0 + 8][kb + lc];
                al[mt][2] = Al[r0    ][kb + 4 + lc];
                al[mt][3] = Al[r0 + 8][kb + 4 + lc];
            }
            #pragma unroll
            for (int nt = 0; nt < 4; nt++) {
                int n0 = wn + nt * 8 + lr;
                bh[nt][0] = Wh[n0][kb + lc];
                bh[nt][1] = Wh[n0][kb + 4 + lc];
                bl[nt][0] = Wl[n0][kb + lc];
                bl[nt][1] = Wl[n0][kb + 4 + lc];
            }
            #pragma unroll
            for (int mt = 0; mt < 4; mt++)
                #pragma unroll
                for (int nt = 0; nt < 4; nt++) {
                    mma_tf32(c[mt][nt], al[mt], bh[nt]);   // small terms first
                    mma_tf32(c[mt][nt], ah[mt], bl[nt]);
                    mma_tf32(c[mt][nt], ah[mt], bh[nt]);
                }
        }
        __syncthreads();
    }

    // Epilogue: add bias, store float2.
    #pragma unroll
    for (int mt = 0; mt < 4; mt++) {
        #pragma unroll
        for (int half = 0; half < 2; half++) {
            int m = bm + wm + mt * 16 + lr + half * 8;
            #pragma unroll
            for (int nt = 0; nt < 4; nt++) {
                int n = bn + wn + nt * 8 + lc * 2;
                float2 bv = *reinterpret_cast<const float2*>(&bias[n]);
                float2 v;
                v.x = c[mt][nt][half * 2 + 0] + bv.x;
                v.y = c[mt][nt][half * 2 + 1] + bv.y;
                *reinterpret_cast<float2*>(&C[(size_t)m * N + n]) = v;
            }
        }
    }
}

// ---------------------------------------------------------------------------
// Scores via TF32 tensor MMA: attn_pre[bh,i,j] = (Q . K) * 0.125
// Block 128x128; 8 warps 2x4; warp 64x32; K=64.  grid (S/128, S/128, B*H)
// ---------------------------------------------------------------------------
__global__ void scores_tc_kernel(float* __restrict__ attn) {
    const int bh = blockIdx.z;
    const int b = bh >> 4;
    const int h = bh & 15;
    const int bm = blockIdx.x * 128;
    const int bn = blockIdx.y * 128;

    __shared__ unsigned Qs[128][36];
    __shared__ unsigned Ks[128][36];

    const int tid = threadIdx.x;
    const int warp = tid >> 5;
    const int lane = tid & 31;
    const int wm = (warp >> 2) * 64;
    const int wn = (warp & 3) * 32;
    const int lr = lane >> 2;
    const int lc = lane & 3;

    float c[4][4][4] = {};

    for (int k0 = 0; k0 < DK; k0 += 32) {
        {
            const int r = tid >> 1;
            const int cb = (tid & 1) * 16;
            const float* src = &g_Q[(size_t)(b * SS + bm + r) * DM + h * DK + k0 + cb];
            #pragma unroll
            for (int i = 0; i < 4; i++) {
                float4 v = *reinterpret_cast<const float4*>(src + i * 4);
                Qs[r][cb + i*4 + 0] = f2tf(v.x);
                Qs[r][cb + i*4 + 1] = f2tf(v.y);
                Qs[r][cb + i*4 + 2] = f2tf(v.z);
                Qs[r][cb + i*4 + 3] = f2tf(v.w);
            }
            const float* ksrc = &g_Kp[(size_t)(b * SS + bn + r) * DK + k0 + cb];
            #pragma unroll
            for (int i = 0; i < 4; i++) {
                float4 v = *reinterpret_cast<const float4*>(ksrc + i * 4);
                Ks[r][cb + i*4 + 0] = f2tf(v.x);
                Ks[r][cb + i*4 + 1] = f2tf(v.y);
                Ks[r][cb + i*4 + 2] = f2tf(v.z);
                Ks[r][cb + i*4 + 3] = f2tf(v.w);
            }
        }
        __syncthreads();

        #pragma unroll
        for (int ks = 0; ks < 4; ks++) {
            const int kb = ks * 8;
            unsigned a[4][4], bf[4][2];
            #pragma unroll
            for (int mt = 0; mt < 4; mt++) {
                int r0 = wm + mt * 16 + lr;
                a[mt][0] = Qs[r0    ][kb + lc];
                a[mt][1] = Qs[r0 + 8][kb + lc];
                a[mt][2] = Qs[r0    ][kb + 4 + lc];
                a[mt][3] = Qs[r0 + 8][kb + 4 + lc];
            }
            #pragma unroll
            for (int nt = 0; nt < 4; nt++) {
                int n0 = wn + nt * 8 + lr;
                bf[nt][0] = Ks[n0][kb + lc];
                bf[nt][1] = Ks[n0][kb + 4 + lc];
            }
            #pragma unroll
            for (int mt = 0; mt < 4; mt++)
                #pragma unroll
                for (int nt = 0; nt < 4; nt++)
                    mma_tf32(c[mt][nt], a[mt], bf[nt]);
        }
        __syncthreads();
    }

    const float scale = 0.125f;
    #pragma unroll
    for (int mt = 0; mt < 4; mt++) {
        #pragma unroll
        for (int half = 0; half < 2; half++) {
            int m = bm + wm + mt * 16 + lr + half * 8;
            size_t rowbase = ((size_t)bh * SS + m) * SS;
            #pragma unroll
            for (int nt = 0; nt < 4; nt++) {
                int n = bn + wn + nt * 8 + lc * 2;
                float2 v;
                v.x = c[mt][nt][half * 2 + 0] * scale;
                v.y = c[mt][nt][half * 2 + 1] * scale;
                *reinterpret_cast<float2*>(&attn[rowbase + n]) = v;
            }
        }
    }
}

// ---------------------------------------------------------------------------
// Row softmax over the last dim (S=2048). One block per row. In-place.
// ---------------------------------------------------------------------------
__global__ void softmax_kernel(float* __restrict__ attn) {
    const size_t row = blockIdx.x;
    float* p = attn + row * SS;
    const int tid = threadIdx.x;

    __shared__ float red[256];

    float v[8];
    float m = -INFINITY;
    #pragma unroll
    for (int i = 0; i < 8; i++) {
        v[i] = p[tid + i * 256];
        m = fmaxf(m, v[i]);
    }
    red[tid] = m;
    __syncthreads();
    #pragma unroll
    for (int s = 128; s > 0; s >>= 1) {
        if (tid < s) red[tid] = fmaxf(red[tid], red[tid + s]);
        __syncthreads();
    }
    m = red[0];
    __syncthreads();

    float sum = 0.f;
    #pragma unroll
    for (int i = 0; i < 8; i++) {
        v[i] = __expf(v[i] - m);
        sum += v[i];
    }
    red[tid] = sum;
    __syncthreads();
    #pragma unroll
    for (int s = 128; s > 0; s >>= 1) {
        if (tid < s) red[tid] += red[tid + s];
        __syncthreads();
    }
    const float inv = 1.f / red[0];

    #pragma unroll
    for (int i = 0; i < 8; i++)
        p[tid + i * 256] = v[i] * inv;
}

// ---------------------------------------------------------------------------
// heads = attn @ V via TF32 MMA, stored in the REFERENCE reshape layout.
// Block 128x64; 8 warps 4x2; warp 32x32; K=S=2048.  grid (S/128, B*H)
// ---------------------------------------------------------------------------
__global__ void av_tc_kernel(const float* __restrict__ attn) {
    const int bh = blockIdx.y;
    const int b = bh >> 4;
    const int h = bh & 15;
    const int bm = blockIdx.x * 128;

    const float* A = attn + (size_t)bh * SS * SS;

    __shared__ unsigned As_[128][36];
    __shared__ unsigned Vs[32][68];

    const int tid = threadIdx.x;
    const int warp = tid >> 5;
    const int lane = tid & 31;
    const int wm = (warp >> 1) * 32;
    const int wn = (warp & 1) * 32;
    const int lr = lane >> 2;
    const int lc = lane & 3;

    float c[2][4][4] = {};

    for (int k0 = 0; k0 < SS; k0 += 32) {
        {
            const int r = tid >> 1;
            const int cb = (tid & 1) * 16;
            const float* src = &A[(size_t)(bm + r) * SS + k0 + cb];
            #pragma unroll
            for (int i = 0; i < 4; i++) {
                float4 v = *reinterpret_cast<const float4*>(src + i * 4);
                As_[r][cb + i*4 + 0] = f2tf(v.x);
                As_[r][cb + i*4 + 1] = f2tf(v.y);
                As_[r][cb + i*4 + 2] = f2tf(v.z);
                As_[r][cb + i*4 + 3] = f2tf(v.w);
            }
        }
        {
            const int r = tid >> 3;
            const int cb = (tid & 7) * 8;
            const float* src = &g_Vp[(size_t)(b * SS + k0 + r) * DK + cb];
            #pragma unroll
            for (int i = 0; i < 2; i++) {
                float4 v = *reinterpret_cast<const float4*>(src + i * 4);
                Vs[r][cb + i*4 + 0] = f2tf(v.x);
                Vs[r][cb + i*4 + 1] = f2tf(v.y);
                Vs[r][cb + i*4 + 2] = f2tf(v.z);
                Vs[r][cb + i*4 + 3] = f2tf(v.w);
            }
        }
        __syncthreads();

        #pragma unroll
        for (int ks = 0; ks < 4; ks++) {
            const int kb = ks * 8;
            unsigned a[2][4], bf[4][2];
            #pragma unroll
            for (int mt = 0; mt < 2; mt++) {
                int r0 = wm + mt * 16 + lr;
                a[mt][0] = As_[r0    ][kb + lc];
                a[mt][1] = As_[r0 + 8][kb + lc];
                a[mt][2] = As_[r0    ][kb + 4 + lc];
                a[mt][3] = As_[r0 + 8][kb + 4 + lc];
            }
            #pragma unroll
            for (int nt = 0; nt < 4; nt++) {
                int n0 = wn + nt * 8 + lr;
                bf[nt][0] = Vs[kb + lc    ][n0];
                bf[nt][1] = Vs[kb + 4 + lc][n0];
            }
            #pragma unroll
            for (int mt = 0; mt < 2; mt++)
                #pragma unroll
                for (int nt = 0; nt < 4; nt++)
                    mma_tf32(c[mt][nt], a[mt], bf[nt]);
        }
        __syncthreads();
    }

    // Scrambled-reshape store (matches reference heads.reshape(B,S,D_MODEL)).
    #pragma unroll
    for (int mt = 0; mt < 2; mt++) {
        #pragma unroll
        for (int half = 0; half < 2; half++) {
            int sq = bm + wm + mt * 16 + lr + half * 8;
            size_t row = (size_t)b * SS + h * 128 + (sq >> 4);
            int cpart = (sq & 15) * 64;
            #pragma unroll
            for (int nt = 0; nt < 4; nt++) {
                int d = wn + nt * 8 + lc * 2;
                float2 v;
                v.x = c[mt][nt][half * 2 + 0];
                v.y = c[mt][nt][half * 2 + 1];
                *reinterpret_cast<float2*>(&g_AO[row * DM + cpart + d]) = v;
            }
        }
    }
}

// ---------------------------------------------------------------------------
// Launch
// ---------------------------------------------------------------------------
extern "C" void kernel_launch(void* const* d_in, const int* in_sizes, int n_in,
                              void* d_out, int out_size) {
    const float* query = (const float*)d_in[0];
    const float* key_  = (const float*)d_in[1];
    const float* value = (const float*)d_in[2];
    const float* w_q   = (const float*)d_in[3];
    const float* b_q   = (const float*)d_in[4];
    const float* w_k   = (const float*)d_in[5];
    const float* b_k   = (const float*)d_in[6];
    const float* w_v   = (const float*)d_in[7];
    const float* b_v   = (const float*)d_in[8];
    const float* w_o   = (const float*)d_in[9];
    const float* b_o   = (const float*)d_in[10];

    float *Qp, *Kp, *Vp, *AO, *attn_scr;
    cudaGetSymbolAddress((void**)&Qp, g_Q);
    cudaGetSymbolAddress((void**)&Kp, g_Kp);
    cudaGetSymbolAddress((void**)&Vp, g_Vp);
    cudaGetSymbolAddress((void**)&AO, g_AO);
    cudaGetSymbolAddress((void**)&attn_scr, g_attn_scratch);

    float* out = (float*)d_out;
    const size_t OUT_ELEMS  = (size_t)BB * SS * DM;
    const size_t ATTN_ELEMS = (size_t)BB * NH * SS * SS;

    float* attn = ((size_t)out_size >= OUT_ELEMS + ATTN_ELEMS)
                      ? (out + OUT_ELEMS)
                      : attn_scr;

    const int M = BB * SS;   // 4096
    dim3 thr(256);

    // Big projections: 3xTF32 tensor cores (near-fp32 accuracy)
    gemm_bias_tf32x3_kernel<<<dim3(M / 128, DM / 128), thr>>>(query, w_q, b_q, Qp, M, DM, DM);
    // Small K/V projections: SIMT fp32
    gemm_bias_kernel<<<dim3(M / 64, 1), thr>>>(key_,  w_k, b_k, Kp, M, DM, DK);
    gemm_bias_kernel<<<dim3(M / 64, 1), thr>>>(value, w_v, b_v, Vp, M, DM, DK);

    // Scores (tf32 tensor core) + softmax
    scores_tc_kernel<<<dim3(SS / 128, SS / 128, BHX), thr>>>(attn);
    softmax_kernel<<<dim3((unsigned)((size_t)BHX * SS)), thr>>>(attn);

    // attn @ V (tf32 tensor core, reference reshape layout)
    av_tc_kernel<<<dim3(SS / 128, BHX), thr>>>(attn);

    // Output projection: 3xTF32 tensor cores
    gemm_bias_tf32x3_kernel<<<dim3(M / 128, DM / 128), thr>>>(AO, w_o, b_o, out, M, DM, DM);
}